// round 12
// baseline (speedup 1.0000x reference)
#include <cuda_runtime.h>
#include <cuda_bf16.h>

// Problem constants
#define TT     64
#define CC     32
#define HDIM   24
#define BB     16384
#define FF     2048
#define HHEAD  48

// Gram tiling
#define CH     16                 // row chunks
#define RPC    (BB / CH)          // 1024 rows per CTA
#define TROWS  128                // rows per smem tile
#define NT     (RPC / TROWS)      // 8 tiles
#define SROWB  80                 // smem row stride bytes (40 bf16): ldmatrix conflict-free
#define TBYTES (TROWS * SROWB)    // 10240 per buffer
#define PRS    34                 // partial row stride (EVEN: float2-aligned)
#define PST    (16 * PRS)         // partial stride per warp (544)

// Scratch (device globals: no allocation allowed). All unique-writer: no zeroing.
__device__ float g_Gp[CH][TT][CC * CC];   // 4MB Gram partials
__device__ float g_sp[CH][TT * CC];       // col-sum partials
__device__ float g_tails[TT];
__device__ int   g_ctrs[TT];              // per-t chunk tickets (static-zero; reset after use)
__device__ int   g_ctr;                   // global head ticket

// ---------------- helpers (sm_80-era only: compiles at plain sm_103) ----------------
__device__ __forceinline__ unsigned smem_u32(const void* p) {
    unsigned a;
    asm("{ .reg .u64 t; cvta.to.shared.u64 t, %1; cvt.u32.u64 %0, t; }" : "=r"(a) : "l"(p));
    return a;
}

__device__ __forceinline__ void ldsm4t(unsigned* r, unsigned addr) {
    asm volatile("ldmatrix.sync.aligned.m8n8.x4.trans.shared.b16 {%0,%1,%2,%3}, [%4];"
                 : "=r"(r[0]), "=r"(r[1]), "=r"(r[2]), "=r"(r[3]) : "r"(addr));
}

__device__ __forceinline__ void mma16816(float* d, const unsigned* a, const unsigned* b) {
    asm volatile(
        "mma.sync.aligned.m16n8k16.row.col.f32.bf16.bf16.f32 "
        "{%0,%1,%2,%3}, {%4,%5,%6,%7}, {%8,%9}, {%0,%1,%2,%3};"
        : "+f"(d[0]), "+f"(d[1]), "+f"(d[2]), "+f"(d[3])
        : "r"(a[0]), "r"(a[1]), "r"(a[2]), "r"(a[3]), "r"(b[0]), "r"(b[1]));
}

// ---------------- Single fused kernel ----------------
// Grid (TT, CH), 256 threads = 8 warps.
// Phase A: gather+convert+Gram via mma.sync (2-tile-ahead register prefetch).
// Phase B: last chunk-CTA per t reduces the (L2-hot) partials -> tail.
// Phase C: last CTA overall computes the 64x48 head.
__global__ void __launch_bounds__(256, 2)
gram_kernel(const float* __restrict__ x,   const int* __restrict__ clusters,
            const float* __restrict__ Wt,  const float* __restrict__ hb,
            const float* __restrict__ vb,  const float* __restrict__ Wh,
            const float* __restrict__ hbh, const float* __restrict__ vbh,
            float* __restrict__ out) {
    __shared__ __align__(16) unsigned char smt[2 * TBYTES];   // 20480B; reused twice
    __shared__ float4 sarr[32][8];                            // col-sum staging
    __shared__ int s_tk;
    float* part = (float*)smt;                                // 8*PST floats = 17408B

    const int tid  = threadIdx.x;
    const int lane = tid & 31;
    const int w    = tid >> 5;
    const int q    = tid & 7;        // col quad (4 cols)
    const int rs   = tid >> 3;       // row slot (0..31)
    const int t    = blockIdx.x;
    const int chunk = blockIdx.y;

    const int cbase = clusters[t * CC];   // contiguous arange layout
    const long rbase = (long)chunk * RPC;
    const float* __restrict__ xp = x + (long)cbase + q * 4;

    // ldmatrix lane offsets (within a buffer); k slab base = w*16
    const int grp = lane >> 3, li = lane & 7;
    const unsigned offA = (unsigned)((w * 16 + (grp >> 1) * 8 + li) * SROWB + (grp & 1) * 16);
    const unsigned offB = (unsigned)((w * 16 + (grp & 1) * 8 + li) * SROWB + (grp >> 1) * 16);
    const unsigned smtu = smem_u32(smt);

    float d[2][4][4];
#pragma unroll
    for (int a = 0; a < 2; a++)
#pragma unroll
        for (int b = 0; b < 4; b++)
#pragma unroll
            for (int k = 0; k < 4; k++) d[a][b][k] = 0.f;

    float4 ssum = make_float4(0.f, 0.f, 0.f, 0.f);
    float4 pfA[4], pfB[4];
#pragma unroll
    for (int j = 0; j < 4; j++) {
        pfA[j] = *(const float4*)&xp[(rbase + rs + 32 * j) * FF];            // tile 0
        pfB[j] = *(const float4*)&xp[(rbase + TROWS + rs + 32 * j) * FF];    // tile 1
    }

    // one tile: store regs->smem (bf16), prefetch tile+2, sync, ldmatrix+mma
    auto do_tile = [&](int tile, float4 (&pf)[4], unsigned char* bp, unsigned base) {
#pragma unroll
        for (int j = 0; j < 4; j++) {
            float4 v = pf[j];
            ssum.x += v.x; ssum.y += v.y; ssum.z += v.z; ssum.w += v.w;
            __nv_bfloat162 p0 = __floats2bfloat162_rn(v.x, v.y);
            __nv_bfloat162 p1 = __floats2bfloat162_rn(v.z, v.w);
            uint2 u;
            u.x = *(unsigned*)&p0;
            u.y = *(unsigned*)&p1;
            *(uint2*)(bp + (rs + 32 * j) * SROWB + q * 8) = u;
        }
        if (tile + 2 < NT) {
            const long rb = rbase + (long)(tile + 2) * TROWS;
#pragma unroll
            for (int j = 0; j < 4; j++)
                pf[j] = *(const float4*)&xp[(rb + rs + 32 * j) * FF];
        }
        __syncthreads();   // one sync/tile; double buffer covers WAR (see R10 proof)

        unsigned a0[4], a1[4], b0[4], b1[4];
        ldsm4t(a0, base + offA);        // A: i cols 0..15
        ldsm4t(a1, base + offA + 32);   // A: i cols 16..31
        ldsm4t(b0, base + offB);        // B: n 0..15
        ldsm4t(b1, base + offB + 32);   // B: n 16..31
        mma16816(d[0][0], a0, &b0[0]);
        mma16816(d[0][1], a0, &b0[2]);
        mma16816(d[0][2], a0, &b1[0]);
        mma16816(d[0][3], a0, &b1[2]);
        mma16816(d[1][0], a1, &b0[0]);
        mma16816(d[1][1], a1, &b0[2]);
        mma16816(d[1][2], a1, &b1[0]);
        mma16816(d[1][3], a1, &b1[2]);
    };

#pragma unroll
    for (int it = 0; it < NT; it += 2) {
        do_tile(it,     pfA, smt,          smtu);
        do_tile(it + 1, pfB, smt + TBYTES, smtu + TBYTES);
    }
    __syncthreads();   // compute done: smt becomes `part`

    sarr[rs][q] = ssum;

    // D fragment (m16n8): c0,c1 -> (row lane/4, col nt*8+(lane%4)*2+{0,1});
    //                     c2,c3 -> row lane/4+8.
    const int r0 = lane >> 2;
    const int jc = (lane & 3) * 2;
    for (int h = 0; h < 2; h++) {      // m halves 0..15 / 16..31
#pragma unroll
        for (int nt = 0; nt < 4; nt++) {
            const int j0 = nt * 8 + jc;
            *(float2*)&part[w * PST + r0 * PRS + j0]       = make_float2(d[h][nt][0], d[h][nt][1]);
            *(float2*)&part[w * PST + (r0 + 8) * PRS + j0] = make_float2(d[h][nt][2], d[h][nt][3]);
        }
        __syncthreads();
        for (int e = tid; e < 512; e += 256) {
            float v = 0.f;
#pragma unroll
            for (int w2 = 0; w2 < 8; w2++)
                v += part[w2 * PST + (e >> 5) * PRS + (e & 31)];
            g_Gp[chunk][t][h * 512 + e] = v;     // unique writer
        }
        if (h == 0 && tid < 32) {
            float v = 0.f;
#pragma unroll
            for (int r2 = 0; r2 < 32; r2++)
                v += ((const float*)&sarr[r2][tid >> 2])[tid & 3];
            g_sp[chunk][t * CC + tid] = v;       // col index == tid
        }
        __syncthreads();
    }

    // ---------- Phase B: per-t ticket; last chunk-CTA finalizes t ----------
    __threadfence();
    __syncthreads();
    if (tid == 0) s_tk = atomicAdd(&g_ctrs[t], 1);
    __syncthreads();
    if (s_tk != CH - 1) return;          // uniform exit
    __threadfence();                     // acquire: see all chunks' partials
    if (tid == 0) g_ctrs[t] = 0;         // reset for next graph replay

    // smem reuse: smt -> finalize buffers
    float* Gs = (float*)smt;             // 1024
    float* Ms = Gs + 1024;               // 768
    float* ss = Ms + 768;                // 32
    float* tl = ss + 32;                 // 64
    float* hh = tl + 64;                 // 48   (total 1936 floats < 5120)
    const int c = tid & 31;

    for (int i = tid; i < CC * HDIM; i += 256) Ms[i] = Wt[t * CC * HDIM + i];
    for (int e = tid; e < CC * CC; e += 256) {
        float v = 0.f;
#pragma unroll
        for (int g = 0; g < CH; g++) v += g_Gp[g][t][e];   // L2-hot
        Gs[e] = v;
    }
    if (tid < CC) {
        float v = 0.f;
#pragma unroll
        for (int g = 0; g < CH; g++) v += g_sp[g][t * CC + tid];
        ss[tid] = v;
    }
    __syncthreads();

    if (tid < 32) {
        float Mc[HDIM];
#pragma unroll
        for (int h = 0; h < HDIM; h++) Mc[h] = Ms[c * HDIM + h];

        float a[CC];
#pragma unroll
        for (int i = 0; i < CC; i++) {
            float accv = 0.f;
#pragma unroll
            for (int h = 0; h < HDIM; h++) accv += Ms[i * HDIM + h] * Mc[h];
            a[i] = (i == c) ? (accv - 1.f) : accv;
        }

        float quad = 0.f, sA = 0.f;
#pragma unroll
        for (int i = 0; i < CC; i++) {
            float dd = 0.f;
#pragma unroll
            for (int j = 0; j < CC; j++) dd += Gs[i * CC + j] * a[j];
            quad += a[i] * dd;
            sA   += ss[i] * a[i];
        }

        float kc = vb[t * CC + c];
#pragma unroll
        for (int h = 0; h < HDIM; h++) kc += hb[t * HDIM + h] * Mc[h];

        float contrib = quad + 2.f * kc * sA + (float)BB * kc * kc;
#pragma unroll
        for (int off = 16; off; off >>= 1)
            contrib += __shfl_xor_sync(0xffffffffu, contrib, off);

        if (c == 0) {
            float msr  = contrib * (1.f / (float)(BB * CC));
            float tail = 0.5f * logf(msr);
            g_tails[t] = tail;
            out[TT + t] = tail;              // tails occupy out[64..127]
        }
    }

    // ---------- Phase C: global ticket; last CTA computes the head ----------
    __threadfence();
    __syncthreads();
    if (tid == 0) s_tk = atomicAdd(&g_ctr, 1);
    __syncthreads();
    if (s_tk != TT - 1) return;          // uniform exit
    __threadfence();                     // acquire: see all g_tails
    if (tid == 0) g_ctr = 0;             // reset for next graph replay

    if (tid < 32) {
#pragma unroll
        for (int i = c; i < TT; i += 32) tl[i] = g_tails[i];
        __syncwarp();
#pragma unroll
        for (int jj = c; jj < HHEAD; jj += 32) {
            float accv = hbh[jj];
#pragma unroll 8
            for (int u = 0; u < TT; u++) accv += tl[u] * Wh[u * HHEAD + jj];
            hh[jj] = accv;
        }
        __syncwarp();
#pragma unroll
        for (int i = c; i < TT; i += 32) {
            float accv = vbh[i];
#pragma unroll 8
            for (int jj = 0; jj < HHEAD; jj++) accv += hh[jj] * Wh[i * HHEAD + jj];
            out[i] = accv;                   // head_out occupies out[0..63]
        }
    }
}

extern "C" void kernel_launch(void* const* d_in, const int* in_sizes, int n_in,
                              void* d_out, int out_size) {
    const float* x        = (const float*)d_in[0];
    const int*   clusters = (const int*)  d_in[1];
    const float* Wt       = (const float*)d_in[2];
    const float* hb       = (const float*)d_in[3];
    const float* vb       = (const float*)d_in[4];
    const float* Wh       = (const float*)d_in[5];
    const float* hbh      = (const float*)d_in[6];
    const float* vbh      = (const float*)d_in[7];
    float* out = (float*)d_out;

    gram_kernel<<<dim3(TT, CH), 256>>>(x, clusters, Wt, hb, vb, Wh, hbh, vbh, out);
}

// round 13
// speedup vs baseline: 1.1922x; 1.1922x over previous
#include <cuda_runtime.h>
#include <cuda_bf16.h>

// Problem constants
#define TT     64
#define CC     32
#define HDIM   24
#define BB     16384
#define FF     2048
#define HHEAD  48

// Gram tiling
#define THREADS 512               // 16 warps
#define CH     2                  // row chunks -> grid 128 CTAs (single wave)
#define RPC    (BB / CH)          // 8192 rows per CTA
#define TROWS  256                // rows per smem tile (16 warps x 16 k-rows)
#define NT     (RPC / TROWS)      // 32 tiles
#define SROWB  80                 // smem row stride bytes: ldmatrix conflict-free
#define TBYTES (TROWS * SROWB)    // 20480 per buffer
#define PRS    34                 // partial row stride (EVEN: float2-aligned)
#define PST    (16 * PRS)         // per-warp partial stride (544)

// Scratch (device globals). All unique-writer: no zeroing needed.
__device__ float g_Gp[CH][TT][CC * CC];   // 512KB Gram partials (L2-resident)
__device__ float g_sp[CH][TT * CC];       // col-sum partials
__device__ float g_tails[TT];
__device__ int   g_ctr;                   // static-zero; last finalize block resets

// ---------------- helpers (sm_80-era only: compiles at plain sm_103) ----------------
__device__ __forceinline__ unsigned smem_u32(const void* p) {
    unsigned a;
    asm("{ .reg .u64 t; cvta.to.shared.u64 t, %1; cvt.u32.u64 %0, t; }" : "=r"(a) : "l"(p));
    return a;
}

__device__ __forceinline__ void ldsm4t(unsigned* r, unsigned addr) {
    asm volatile("ldmatrix.sync.aligned.m8n8.x4.trans.shared.b16 {%0,%1,%2,%3}, [%4];"
                 : "=r"(r[0]), "=r"(r[1]), "=r"(r[2]), "=r"(r[3]) : "r"(addr));
}

__device__ __forceinline__ void mma16816(float* d, const unsigned* a, const unsigned* b) {
    asm volatile(
        "mma.sync.aligned.m16n8k16.row.col.f32.bf16.bf16.f32 "
        "{%0,%1,%2,%3}, {%4,%5,%6,%7}, {%8,%9}, {%0,%1,%2,%3};"
        : "+f"(d[0]), "+f"(d[1]), "+f"(d[2]), "+f"(d[3])
        : "r"(a[0]), "r"(a[1]), "r"(a[2]), "r"(a[3]), "r"(b[0]), "r"(b[1]));
}

// ---------------- Kernel 1: fused gather+convert+Gram via mma.sync ----------------
// Grid (TT, CH), 512 threads. Warp w consumes k-rows w*16..+15 of each 256-row tile.
// Symmetry: compute D rows 0-15 (all cols) + rows 16-31 (cols 16-31); reconstruct
// rows 16-31 / cols 0-15 by transposing d0[2..3] in the epilogue.
__global__ void __launch_bounds__(THREADS)
gram_kernel(const float* __restrict__ x, const int* __restrict__ clusters) {
    __shared__ __align__(16) unsigned char smt[2 * TBYTES];   // 40960B; reused as `part`
    __shared__ float4 swsum[16][8];                           // per-warp col-sum partials
    float* part = (float*)smt;                                // 16*PST floats = 34816B

    const int tid  = threadIdx.x;
    const int lane = tid & 31;
    const int w    = tid >> 5;       // 0..15
    const int q    = tid & 7;        // col quad (4 cols)
    const int rs   = tid >> 3;       // row slot (0..63)
    const int t    = blockIdx.x;
    const int chunk = blockIdx.y;

    const int cbase = clusters[t * CC];   // contiguous arange layout
    const long rbase = (long)chunk * RPC;
    const float* __restrict__ xp = x + (long)cbase + q * 4;

    // ldmatrix lane offsets (within a buffer); k slab base = w*16
    const int grp = lane >> 3, li = lane & 7;
    const unsigned offA = (unsigned)((w * 16 + (grp >> 1) * 8 + li) * SROWB + (grp & 1) * 16);
    const unsigned offB = (unsigned)((w * 16 + (grp & 1) * 8 + li) * SROWB + (grp >> 1) * 16);
    const unsigned smtu = smem_u32(smt);

    float d0[4][4], d1[2][4];
#pragma unroll
    for (int b = 0; b < 4; b++)
#pragma unroll
        for (int k = 0; k < 4; k++) d0[b][k] = 0.f;
#pragma unroll
    for (int b = 0; b < 2; b++)
#pragma unroll
        for (int k = 0; k < 4; k++) d1[b][k] = 0.f;

    float4 ssum = make_float4(0.f, 0.f, 0.f, 0.f);
    float4 pfA[4], pfB[4];
#pragma unroll
    for (int j = 0; j < 4; j++) {
        pfA[j] = *(const float4*)&xp[(rbase + rs + 64 * j) * FF];            // tile 0
        pfB[j] = *(const float4*)&xp[(rbase + TROWS + rs + 64 * j) * FF];    // tile 1
    }

    // one tile: store regs->smem (bf16), prefetch tile+2 (true 2-deep), sync, mma
    auto do_tile = [&](int tile, float4 (&pf)[4], unsigned char* bp, unsigned base) {
#pragma unroll
        for (int j = 0; j < 4; j++) {
            float4 v = pf[j];
            ssum.x += v.x; ssum.y += v.y; ssum.z += v.z; ssum.w += v.w;
            __nv_bfloat162 p0 = __floats2bfloat162_rn(v.x, v.y);
            __nv_bfloat162 p1 = __floats2bfloat162_rn(v.z, v.w);
            uint2 u;
            u.x = *(unsigned*)&p0;
            u.y = *(unsigned*)&p1;
            *(uint2*)(bp + (rs + 64 * j) * SROWB + q * 8) = u;
        }
        if (tile + 2 < NT) {
            const long rb = rbase + (long)(tile + 2) * TROWS;
#pragma unroll
            for (int j = 0; j < 4; j++)
                pf[j] = *(const float4*)&xp[(rb + rs + 64 * j) * FF];
        }
        __syncthreads();   // one sync/tile; double buffer covers WAR

        unsigned a0[4], a1[4], b0[4], b1[4];
        ldsm4t(a0, base + offA);        // A: i cols 0..15
        ldsm4t(a1, base + offA + 32);   // A: i cols 16..31
        ldsm4t(b0, base + offB);        // B: n 0..15
        ldsm4t(b1, base + offB + 32);   // B: n 16..31
        mma16816(d0[0], a0, &b0[0]);
        mma16816(d0[1], a0, &b0[2]);
        mma16816(d0[2], a0, &b1[0]);
        mma16816(d0[3], a0, &b1[2]);
        mma16816(d1[0], a1, &b1[0]);    // rows 16-31, cols 16-23
        mma16816(d1[1], a1, &b1[2]);    // rows 16-31, cols 24-31
    };

#pragma unroll 1
    for (int it = 0; it < NT; it += 2) {
        do_tile(it,     pfA, smt,          smtu);
        do_tile(it + 1, pfB, smt + TBYTES, smtu + TBYTES);
    }

    // column sums: reduce across the 4 lane-replicas of each quad (lane bits 3,4)
#pragma unroll
    for (int off = 8; off <= 16; off <<= 1) {
        ssum.x += __shfl_xor_sync(0xffffffffu, ssum.x, off);
        ssum.y += __shfl_xor_sync(0xffffffffu, ssum.y, off);
        ssum.z += __shfl_xor_sync(0xffffffffu, ssum.z, off);
        ssum.w += __shfl_xor_sync(0xffffffffu, ssum.w, off);
    }
    if (lane < 8) swsum[w][lane] = ssum;
    __syncthreads();   // compute done: smt becomes `part`

    // D fragment (m16n8): c0,c1 -> (row r0, col nt*8+jc+{0,1}); c2,c3 -> row r0+8.
    const int r0 = lane >> 2;
    const int jc = (lane & 3) * 2;

    // ---- h = 0: Gram rows 0..15 (all from d0) ----
#pragma unroll
    for (int nt = 0; nt < 4; nt++) {
        const int j0 = nt * 8 + jc;
        *(float2*)&part[w * PST + r0 * PRS + j0]       = make_float2(d0[nt][0], d0[nt][1]);
        *(float2*)&part[w * PST + (r0 + 8) * PRS + j0] = make_float2(d0[nt][2], d0[nt][3]);
    }
    __syncthreads();
    {
        const int e = tid;   // 512 elements, 512 threads
        float v = 0.f;
#pragma unroll
        for (int w2 = 0; w2 < 16; w2++)
            v += part[w2 * PST + (e >> 5) * PRS + (e & 31)];
        g_Gp[chunk][t][e] = v;                        // unique writer
    }
    if (tid < 32) {
        float v = 0.f;
#pragma unroll
        for (int w2 = 0; w2 < 16; w2++)
            v += ((const float*)&swsum[w2][tid >> 2])[tid & 3];
        g_sp[chunk][t * CC + tid] = v;                // col index == tid
    }
    __syncthreads();

    // ---- h = 1: Gram rows 16..31 ----
    // cols 16..31 from d1; cols 0..15 from TRANSPOSED d0[2..3] (G symmetric)
#pragma unroll
    for (int nt2 = 0; nt2 < 2; nt2++) {
        const int j0 = (nt2 + 2) * 8 + jc;
        *(float2*)&part[w * PST + r0 * PRS + j0]       = make_float2(d1[nt2][0], d1[nt2][1]);
        *(float2*)&part[w * PST + (r0 + 8) * PRS + j0] = make_float2(d1[nt2][2], d1[nt2][3]);
    }
#pragma unroll
    for (int nt = 2; nt < 4; nt++)
#pragma unroll
        for (int k = 0; k < 4; k++) {
            const int col_o = nt * 8 + jc + (k & 1);          // 16..31
            const int row_o = r0 + 8 * (k >> 1);              // 0..15
            part[w * PST + (col_o - 16) * PRS + row_o] = d0[nt][k];
        }
    __syncthreads();
    {
        const int e = tid;
        float v = 0.f;
#pragma unroll
        for (int w2 = 0; w2 < 16; w2++)
            v += part[w2 * PST + (e >> 5) * PRS + (e & 31)];
        g_Gp[chunk][t][512 + e] = v;                  // unique writer
    }
}

// ---------------- Kernel 2: finalize (tails) + fused head on last block ----------------
#define FB 256
__global__ void __launch_bounds__(FB)
finalize_kernel(const float* __restrict__ Wt,  const float* __restrict__ hb,
                const float* __restrict__ vb,  const float* __restrict__ Wh,
                const float* __restrict__ hbh, const float* __restrict__ vbh,
                float* __restrict__ out) {
    const int t   = blockIdx.x;
    const int tid = threadIdx.x;
    const int c   = tid & 31;

    __shared__ float Gs[CC * CC];
    __shared__ float ss[CC];
    __shared__ float Ms[CC * HDIM];
    __shared__ float tl[TT];
    __shared__ float hh[HHEAD];

    for (int i = tid; i < CC * HDIM; i += FB) Ms[i] = Wt[t * CC * HDIM + i];
    for (int e = tid; e < CC * CC; e += FB) {
        float v = 0.f;
#pragma unroll
        for (int g = 0; g < CH; g++) v += g_Gp[g][t][e];   // L2-hot
        Gs[e] = v;
    }
    if (tid < CC) {
        float v = 0.f;
#pragma unroll
        for (int g = 0; g < CH; g++) v += g_sp[g][t * CC + tid];
        ss[tid] = v;
    }
    __syncthreads();

    if (tid < 32) {
        float Mc[HDIM];
#pragma unroll
        for (int h = 0; h < HDIM; h++) Mc[h] = Ms[c * HDIM + h];

        float a[CC];
#pragma unroll
        for (int i = 0; i < CC; i++) {
            float accv = 0.f;
#pragma unroll
            for (int h = 0; h < HDIM; h++) accv += Ms[i * HDIM + h] * Mc[h];
            a[i] = (i == c) ? (accv - 1.f) : accv;
        }

        float quad = 0.f, sA = 0.f;
#pragma unroll
        for (int i = 0; i < CC; i++) {
            float dd = 0.f;
#pragma unroll
            for (int j = 0; j < CC; j++) dd += Gs[i * CC + j] * a[j];
            quad += a[i] * dd;
            sA   += ss[i] * a[i];
        }

        float kc = vb[t * CC + c];
#pragma unroll
        for (int h = 0; h < HDIM; h++) kc += hb[t * HDIM + h] * Mc[h];

        float contrib = quad + 2.f * kc * sA + (float)BB * kc * kc;
#pragma unroll
        for (int off = 16; off; off >>= 1)
            contrib += __shfl_xor_sync(0xffffffffu, contrib, off);

        if (c == 0) {
            float msr  = contrib * (1.f / (float)(BB * CC));
            float tail = 0.5f * logf(msr);
            g_tails[t] = tail;
            out[TT + t] = tail;                // tails occupy out[64..127]
        }
    }

    // ---- last block computes the head ----
    __threadfence();
    __syncthreads();
    __shared__ int s_tk;
    if (tid == 0) s_tk = atomicAdd(&g_ctr, 1);
    __syncthreads();
    if (s_tk != TT - 1) return;
    __threadfence();                           // acquire: see all g_tails
    if (tid == 0) g_ctr = 0;                   // reset for next graph replay

    if (tid < 32) {
#pragma unroll
        for (int i = c; i < TT; i += 32) tl[i] = g_tails[i];
        __syncwarp();
#pragma unroll
        for (int jj = c; jj < HHEAD; jj += 32) {
            float accv = hbh[jj];
#pragma unroll 8
            for (int u = 0; u < TT; u++) accv += tl[u] * Wh[u * HHEAD + jj];
            hh[jj] = accv;
        }
        __syncwarp();
#pragma unroll
        for (int i = c; i < TT; i += 32) {
            float accv = vbh[i];
#pragma unroll 8
            for (int jj = 0; jj < HHEAD; jj++) accv += hh[jj] * Wh[i * HHEAD + jj];
            out[i] = accv;                     // head_out occupies out[0..63]
        }
    }
}

extern "C" void kernel_launch(void* const* d_in, const int* in_sizes, int n_in,
                              void* d_out, int out_size) {
    const float* x        = (const float*)d_in[0];
    const int*   clusters = (const int*)  d_in[1];
    const float* Wt       = (const float*)d_in[2];
    const float* hb       = (const float*)d_in[3];
    const float* vb       = (const float*)d_in[4];
    const float* Wh       = (const float*)d_in[5];
    const float* hbh      = (const float*)d_in[6];
    const float* vbh      = (const float*)d_in[7];
    float* out = (float*)d_out;

    gram_kernel<<<dim3(TT, CH), THREADS>>>(x, clusters);
    finalize_kernel<<<TT, FB>>>(Wt, hb, vb, Wh, hbh, vbh, out);
}

// round 14
// speedup vs baseline: 1.3412x; 1.1250x over previous
#include <cuda_runtime.h>
#include <cuda_bf16.h>

// Problem constants
#define TT     64
#define CC     32
#define HDIM   24
#define BB     16384
#define FF     2048
#define HHEAD  48

// Gram tiling
#define THREADS 512               // 16 warps
#define CH     2                  // row chunks -> grid 128 CTAs (single wave)
#define RPC    (BB / CH)          // 8192 rows per CTA
#define TROWS  256                // rows per smem tile (16 warps x 16 k-rows)
#define NT     (RPC / TROWS)      // 32 tiles
#define SROWB  80                 // smem row stride bytes: ldmatrix conflict-free
#define TBYTES (TROWS * SROWB)    // 20480 per buffer
#define PRS    34                 // partial row stride (EVEN: float2-aligned)
#define PST    (16 * PRS)         // per-warp partial stride (544)

// Scratch (device globals). All unique-writer: no zeroing needed.
__device__ float g_Gp[CH][TT][CC * CC];   // 512KB Gram partials (L2-resident)
__device__ float g_sp[CH][TT * CC];       // col-sum partials
__device__ float g_tails[TT];
__device__ int   g_ctr;                   // static-zero; last finalize block resets

// ---------------- helpers (sm_80-era only: compiles at plain sm_103) ----------------
__device__ __forceinline__ unsigned smem_u32(const void* p) {
    unsigned a;
    asm("{ .reg .u64 t; cvta.to.shared.u64 t, %1; cvt.u32.u64 %0, t; }" : "=r"(a) : "l"(p));
    return a;
}

__device__ __forceinline__ void ldsm4t(unsigned* r, unsigned addr) {
    asm volatile("ldmatrix.sync.aligned.m8n8.x4.trans.shared.b16 {%0,%1,%2,%3}, [%4];"
                 : "=r"(r[0]), "=r"(r[1]), "=r"(r[2]), "=r"(r[3]) : "r"(addr));
}

__device__ __forceinline__ void mma16816(float* d, const unsigned* a, const unsigned* b) {
    asm volatile(
        "mma.sync.aligned.m16n8k16.row.col.f32.bf16.bf16.f32 "
        "{%0,%1,%2,%3}, {%4,%5,%6,%7}, {%8,%9}, {%0,%1,%2,%3};"
        : "+f"(d[0]), "+f"(d[1]), "+f"(d[2]), "+f"(d[3])
        : "r"(a[0]), "r"(a[1]), "r"(a[2]), "r"(a[3]), "r"(b[0]), "r"(b[1]));
}

// ---------------- Kernel 1: fused gather+convert+Gram via mma.sync ----------------
// (unchanged from R13 win)
__global__ void __launch_bounds__(THREADS)
gram_kernel(const float* __restrict__ x, const int* __restrict__ clusters) {
    __shared__ __align__(16) unsigned char smt[2 * TBYTES];   // 40960B; reused as `part`
    __shared__ float4 swsum[16][8];                           // per-warp col-sum partials
    float* part = (float*)smt;                                // 16*PST floats = 34816B

    const int tid  = threadIdx.x;
    const int lane = tid & 31;
    const int w    = tid >> 5;       // 0..15
    const int q    = tid & 7;        // col quad (4 cols)
    const int rs   = tid >> 3;       // row slot (0..63)
    const int t    = blockIdx.x;
    const int chunk = blockIdx.y;

    const int cbase = clusters[t * CC];   // contiguous arange layout
    const long rbase = (long)chunk * RPC;
    const float* __restrict__ xp = x + (long)cbase + q * 4;

    const int grp = lane >> 3, li = lane & 7;
    const unsigned offA = (unsigned)((w * 16 + (grp >> 1) * 8 + li) * SROWB + (grp & 1) * 16);
    const unsigned offB = (unsigned)((w * 16 + (grp & 1) * 8 + li) * SROWB + (grp >> 1) * 16);
    const unsigned smtu = smem_u32(smt);

    float d0[4][4], d1[2][4];
#pragma unroll
    for (int b = 0; b < 4; b++)
#pragma unroll
        for (int k = 0; k < 4; k++) d0[b][k] = 0.f;
#pragma unroll
    for (int b = 0; b < 2; b++)
#pragma unroll
        for (int k = 0; k < 4; k++) d1[b][k] = 0.f;

    float4 ssum = make_float4(0.f, 0.f, 0.f, 0.f);
    float4 pfA[4], pfB[4];
#pragma unroll
    for (int j = 0; j < 4; j++) {
        pfA[j] = *(const float4*)&xp[(rbase + rs + 64 * j) * FF];            // tile 0
        pfB[j] = *(const float4*)&xp[(rbase + TROWS + rs + 64 * j) * FF];    // tile 1
    }

    auto do_tile = [&](int tile, float4 (&pf)[4], unsigned char* bp, unsigned base) {
#pragma unroll
        for (int j = 0; j < 4; j++) {
            float4 v = pf[j];
            ssum.x += v.x; ssum.y += v.y; ssum.z += v.z; ssum.w += v.w;
            __nv_bfloat162 p0 = __floats2bfloat162_rn(v.x, v.y);
            __nv_bfloat162 p1 = __floats2bfloat162_rn(v.z, v.w);
            uint2 u;
            u.x = *(unsigned*)&p0;
            u.y = *(unsigned*)&p1;
            *(uint2*)(bp + (rs + 64 * j) * SROWB + q * 8) = u;
        }
        if (tile + 2 < NT) {
            const long rb = rbase + (long)(tile + 2) * TROWS;
#pragma unroll
            for (int j = 0; j < 4; j++)
                pf[j] = *(const float4*)&xp[(rb + rs + 64 * j) * FF];
        }
        __syncthreads();

        unsigned a0[4], a1[4], b0[4], b1[4];
        ldsm4t(a0, base + offA);
        ldsm4t(a1, base + offA + 32);
        ldsm4t(b0, base + offB);
        ldsm4t(b1, base + offB + 32);
        mma16816(d0[0], a0, &b0[0]);
        mma16816(d0[1], a0, &b0[2]);
        mma16816(d0[2], a0, &b1[0]);
        mma16816(d0[3], a0, &b1[2]);
        mma16816(d1[0], a1, &b1[0]);
        mma16816(d1[1], a1, &b1[2]);
    };

#pragma unroll 1
    for (int it = 0; it < NT; it += 2) {
        do_tile(it,     pfA, smt,          smtu);
        do_tile(it + 1, pfB, smt + TBYTES, smtu + TBYTES);
    }

#pragma unroll
    for (int off = 8; off <= 16; off <<= 1) {
        ssum.x += __shfl_xor_sync(0xffffffffu, ssum.x, off);
        ssum.y += __shfl_xor_sync(0xffffffffu, ssum.y, off);
        ssum.z += __shfl_xor_sync(0xffffffffu, ssum.z, off);
        ssum.w += __shfl_xor_sync(0xffffffffu, ssum.w, off);
    }
    if (lane < 8) swsum[w][lane] = ssum;
    __syncthreads();   // compute done: smt becomes `part`

    const int r0 = lane >> 2;
    const int jc = (lane & 3) * 2;

    // ---- h = 0: Gram rows 0..15 ----
#pragma unroll
    for (int nt = 0; nt < 4; nt++) {
        const int j0 = nt * 8 + jc;
        *(float2*)&part[w * PST + r0 * PRS + j0]       = make_float2(d0[nt][0], d0[nt][1]);
        *(float2*)&part[w * PST + (r0 + 8) * PRS + j0] = make_float2(d0[nt][2], d0[nt][3]);
    }
    __syncthreads();
    {
        const int e = tid;
        float v = 0.f;
#pragma unroll
        for (int w2 = 0; w2 < 16; w2++)
            v += part[w2 * PST + (e >> 5) * PRS + (e & 31)];
        g_Gp[chunk][t][e] = v;
    }
    if (tid < 32) {
        float v = 0.f;
#pragma unroll
        for (int w2 = 0; w2 < 16; w2++)
            v += ((const float*)&swsum[w2][tid >> 2])[tid & 3];
        g_sp[chunk][t * CC + tid] = v;
    }
    __syncthreads();

    // ---- h = 1: Gram rows 16..31 (cols 0..15 via symmetry transpose) ----
#pragma unroll
    for (int nt2 = 0; nt2 < 2; nt2++) {
        const int j0 = (nt2 + 2) * 8 + jc;
        *(float2*)&part[w * PST + r0 * PRS + j0]       = make_float2(d1[nt2][0], d1[nt2][1]);
        *(float2*)&part[w * PST + (r0 + 8) * PRS + j0] = make_float2(d1[nt2][2], d1[nt2][3]);
    }
#pragma unroll
    for (int nt = 2; nt < 4; nt++)
#pragma unroll
        for (int k = 0; k < 4; k++) {
            const int col_o = nt * 8 + jc + (k & 1);
            const int row_o = r0 + 8 * (k >> 1);
            part[w * PST + (col_o - 16) * PRS + row_o] = d0[nt][k];
        }
    __syncthreads();
    {
        const int e = tid;
        float v = 0.f;
#pragma unroll
        for (int w2 = 0; w2 < 16; w2++)
            v += part[w2 * PST + (e >> 5) * PRS + (e & 31)];
        g_Gp[chunk][t][512 + e] = v;
    }
}

// ---------------- Kernel 2: finalize v2 (trace form, all 256 threads) ----------------
// Total SSR over c:  <G, A*A> + 2 s^T A k + B |k|^2,  A = M M^T - I (symmetric).
#define FB 256
#define MSR 25   // padded Ms row stride: (4*MSR) mod 32 = 4 -> conflict-free j-group loads
__global__ void __launch_bounds__(FB)
finalize_kernel(const float* __restrict__ Wt,  const float* __restrict__ hb,
                const float* __restrict__ vb,  const float* __restrict__ Wh,
                const float* __restrict__ hbh, const float* __restrict__ vbh,
                float* __restrict__ out) {
    const int t    = blockIdx.x;
    const int tid  = threadIdx.x;
    const int lane = tid & 31;
    const int w    = tid >> 5;

    __shared__ float Ms[CC * MSR];       // padded 32x24
    __shared__ float Gs[CC * CC];
    __shared__ float As[CC][CC + 1];     // A = MM^T - I, padded
    __shared__ float ss[CC], ks[CC];
    __shared__ float red[8];
    __shared__ float tl[TT], hh[HHEAD];

    for (int idx = tid; idx < CC * HDIM; idx += FB)
        Ms[(idx / HDIM) * MSR + (idx % HDIM)] = Wt[t * CC * HDIM + idx];
    for (int e = tid; e < CC * CC; e += FB) {
        float v = 0.f;
#pragma unroll
        for (int g = 0; g < CH; g++) v += g_Gp[g][t][e];   // L2-hot
        Gs[e] = v;
    }
    if (tid < CC) {
        float v = 0.f;
#pragma unroll
        for (int g = 0; g < CH; g++) v += g_sp[g][t * CC + tid];
        ss[tid] = v;
    }
    __syncthreads();

    const int i  = tid >> 3;         // 0..31
    const int j0 = (tid & 7) * 4;    // 0,4,...,28

    // k vector (warp 0)
    if (tid < CC) {
        float kc = vb[t * CC + tid];
#pragma unroll
        for (int h = 0; h < HDIM; h++) kc += hb[t * HDIM + h] * Ms[tid * MSR + h];
        ks[tid] = kc;
    }

    // A = M M^T - I : each thread 4 elements (i, j0..j0+3)
    {
        float acc[4] = {0.f, 0.f, 0.f, 0.f};
#pragma unroll
        for (int h = 0; h < HDIM; h++) {
            float mi = Ms[i * MSR + h];
#pragma unroll
            for (int u = 0; u < 4; u++) acc[u] += mi * Ms[(j0 + u) * MSR + h];
        }
#pragma unroll
        for (int u = 0; u < 4; u++)
            As[i][j0 + u] = acc[u] - ((i == j0 + u) ? 1.f : 0.f);
    }
    __syncthreads();

    // quad partial: P_ij = row_i(A) . row_j(A)  (A symmetric), contrib += G_ij * P_ij
    float part = 0.f;
    {
        float acc[4] = {0.f, 0.f, 0.f, 0.f};
#pragma unroll
        for (int l = 0; l < CC; l++) {
            float ai = As[i][l];
#pragma unroll
            for (int u = 0; u < 4; u++) acc[u] += ai * As[j0 + u][l];
        }
#pragma unroll
        for (int u = 0; u < 4; u++) part += Gs[i * CC + j0 + u] * acc[u];
    }
    // linear + constant terms (warp 0): k_c * (2 (A s)_c + B k_c)
    if (tid < CC) {
        float vs = 0.f;
#pragma unroll
        for (int l = 0; l < CC; l++) vs += As[tid][l] * ss[l];
        part += ks[tid] * (2.f * vs + (float)BB * ks[tid]);
    }

    // block reduction
#pragma unroll
    for (int off = 16; off; off >>= 1)
        part += __shfl_xor_sync(0xffffffffu, part, off);
    if (lane == 0) red[w] = part;
    __syncthreads();
    if (tid == 0) {
        float ssr = 0.f;
#pragma unroll
        for (int ww = 0; ww < 8; ww++) ssr += red[ww];
        float msr  = ssr * (1.f / (float)(BB * CC));
        float tail = 0.5f * logf(msr);
        g_tails[t] = tail;
        out[TT + t] = tail;                    // tails occupy out[64..127]
    }

    // ---- last block computes the head ----
    __threadfence();
    __syncthreads();
    __shared__ int s_tk;
    if (tid == 0) s_tk = atomicAdd(&g_ctr, 1);
    __syncthreads();
    if (s_tk != TT - 1) return;
    __threadfence();                           // acquire: see all g_tails
    if (tid == 0) g_ctr = 0;                   // reset for next graph replay

    if (tid < TT) tl[tid] = g_tails[tid];
    __syncthreads();
    if (tid < HHEAD) {
        float accv = hbh[tid];
#pragma unroll 8
        for (int u = 0; u < TT; u++) accv += tl[u] * Wh[u * HHEAD + tid];
        hh[tid] = accv;
    }
    __syncthreads();
    if (tid < TT) {
        float accv = vbh[tid];
#pragma unroll 8
        for (int jj = 0; jj < HHEAD; jj++) accv += hh[jj] * Wh[tid * HHEAD + jj];
        out[tid] = accv;                       // head_out occupies out[0..63]
    }
}

extern "C" void kernel_launch(void* const* d_in, const int* in_sizes, int n_in,
                              void* d_out, int out_size) {
    const float* x        = (const float*)d_in[0];
    const int*   clusters = (const int*)  d_in[1];
    const float* Wt       = (const float*)d_in[2];
    const float* hb       = (const float*)d_in[3];
    const float* vb       = (const float*)d_in[4];
    const float* Wh       = (const float*)d_in[5];
    const float* hbh      = (const float*)d_in[6];
    const float* vbh      = (const float*)d_in[7];
    float* out = (float*)d_out;

    gram_kernel<<<dim3(TT, CH), THREADS>>>(x, clusters);
    finalize_kernel<<<TT, FB>>>(Wt, hb, vb, Wh, hbh, vbh, out);
}

// round 17
// speedup vs baseline: 1.3587x; 1.0130x over previous
#include <cuda_runtime.h>
#include <cuda_bf16.h>

// Problem constants
#define TT     64
#define CC     32
#define HDIM   24
#define BB     16384
#define FF     2048
#define HHEAD  48

// Gram tiling
#define THREADS 512               // 16 warps
#define CH     2                  // row chunks -> grid 128 CTAs (single wave)
#define RPC    (BB / CH)          // 8192 rows per CTA
#define TROWS  256                // rows per smem tile (16 warps x 16 k-rows)
#define NT     (RPC / TROWS)      // 32 tiles
#define SROWB  80                 // smem row stride bytes: ldmatrix conflict-free
#define TBYTES (TROWS * SROWB)    // 20480 per buffer
#define PRS    34                 // partial row stride (EVEN: float2-aligned)
#define PST    (16 * PRS)         // per-warp partial stride (544)
#define MSR    25                 // padded Ms row stride (finalize)

// Scratch (device globals). All unique-writer: no zeroing needed.
__device__ float g_Gp[CH][TT][CC * CC];   // 512KB Gram partials (L2-resident)
__device__ float g_sp[CH][TT * CC];       // col-sum partials
__device__ float g_tails[TT];
__device__ int   g_ctrs[TT];              // per-t chunk tickets (static-zero; reset after use)
__device__ int   g_ctr;                   // global head ticket (static-zero; reset after use)

// ---------------- helpers (sm_80-era only: compiles at plain sm_103) ----------------
__device__ __forceinline__ unsigned smem_u32(const void* p) {
    unsigned a;
    asm("{ .reg .u64 t; cvta.to.shared.u64 t, %1; cvt.u32.u64 %0, t; }" : "=r"(a) : "l"(p));
    return a;
}

__device__ __forceinline__ void ldsm4t(unsigned* r, unsigned addr) {
    asm volatile("ldmatrix.sync.aligned.m8n8.x4.trans.shared.b16 {%0,%1,%2,%3}, [%4];"
                 : "=r"(r[0]), "=r"(r[1]), "=r"(r[2]), "=r"(r[3]) : "r"(addr));
}

__device__ __forceinline__ void mma16816(float* d, const unsigned* a, const unsigned* b) {
    asm volatile(
        "mma.sync.aligned.m16n8k16.row.col.f32.bf16.bf16.f32 "
        "{%0,%1,%2,%3}, {%4,%5,%6,%7}, {%8,%9}, {%0,%1,%2,%3};"
        : "+f"(d[0]), "+f"(d[1]), "+f"(d[2]), "+f"(d[3])
        : "r"(a[0]), "r"(a[1]), "r"(a[2]), "r"(a[3]), "r"(b[0]), "r"(b[1]));
}

// ---------------- Single fused kernel ----------------
// Grid (TT, CH), 512 threads.
// Phase A: gather+convert+Gram via mma.sync (R13/R14 winning mainloop, unchanged).
// Phase B: last chunk-CTA per t runs trace-form finalize on L2-hot partials -> tail.
// Phase C: last finalizing CTA computes the 64x48 head.
__global__ void __launch_bounds__(THREADS)
gram_kernel(const float* __restrict__ x,   const int* __restrict__ clusters,
            const float* __restrict__ Wt,  const float* __restrict__ hb,
            const float* __restrict__ vb,  const float* __restrict__ Wh,
            const float* __restrict__ hbh, const float* __restrict__ vbh,
            float* __restrict__ out) {
    __shared__ __align__(16) unsigned char smt[2 * TBYTES];   // 40960B; reused 2x
    __shared__ float4 swsum[16][8];                           // per-warp col-sum partials
    __shared__ int s_tk;
    float* part = (float*)smt;                                // 16*PST floats = 34816B

    const int tid  = threadIdx.x;
    const int lane = tid & 31;
    const int w    = tid >> 5;       // 0..15
    const int q    = tid & 7;        // col quad (4 cols)
    const int rs   = tid >> 3;       // row slot (0..63)
    const int t    = blockIdx.x;
    const int chunk = blockIdx.y;

    const int cbase = clusters[t * CC];   // contiguous arange layout
    const long rbase = (long)chunk * RPC;
    const float* __restrict__ xp = x + (long)cbase + q * 4;

    const int grp = lane >> 3, li = lane & 7;
    const unsigned offA = (unsigned)((w * 16 + (grp >> 1) * 8 + li) * SROWB + (grp & 1) * 16);
    const unsigned offB = (unsigned)((w * 16 + (grp & 1) * 8 + li) * SROWB + (grp >> 1) * 16);
    const unsigned smtu = smem_u32(smt);

    float d0[4][4], d1[2][4];
#pragma unroll
    for (int b = 0; b < 4; b++)
#pragma unroll
        for (int k = 0; k < 4; k++) d0[b][k] = 0.f;
#pragma unroll
    for (int b = 0; b < 2; b++)
#pragma unroll
        for (int k = 0; k < 4; k++) d1[b][k] = 0.f;

    float4 ssum = make_float4(0.f, 0.f, 0.f, 0.f);
    float4 pfA[4], pfB[4];
#pragma unroll
    for (int j = 0; j < 4; j++) {
        pfA[j] = *(const float4*)&xp[(rbase + rs + 64 * j) * FF];            // tile 0
        pfB[j] = *(const float4*)&xp[(rbase + TROWS + rs + 64 * j) * FF];    // tile 1
    }

    auto do_tile = [&](int tile, float4 (&pf)[4], unsigned char* bp, unsigned base) {
#pragma unroll
        for (int j = 0; j < 4; j++) {
            float4 v = pf[j];
            ssum.x += v.x; ssum.y += v.y; ssum.z += v.z; ssum.w += v.w;
            __nv_bfloat162 p0 = __floats2bfloat162_rn(v.x, v.y);
            __nv_bfloat162 p1 = __floats2bfloat162_rn(v.z, v.w);
            uint2 u;
            u.x = *(unsigned*)&p0;
            u.y = *(unsigned*)&p1;
            *(uint2*)(bp + (rs + 64 * j) * SROWB + q * 8) = u;
        }
        if (tile + 2 < NT) {
            const long rb = rbase + (long)(tile + 2) * TROWS;
#pragma unroll
            for (int j = 0; j < 4; j++)
                pf[j] = *(const float4*)&xp[(rb + rs + 64 * j) * FF];
        }
        __syncthreads();   // one sync/tile; double buffer covers WAR

        unsigned a0[4], a1[4], b0[4], b1[4];
        ldsm4t(a0, base + offA);        // A: i cols 0..15
        ldsm4t(a1, base + offA + 32);   // A: i cols 16..31
        ldsm4t(b0, base + offB);        // B: n 0..15
        ldsm4t(b1, base + offB + 32);   // B: n 16..31
        mma16816(d0[0], a0, &b0[0]);
        mma16816(d0[1], a0, &b0[2]);
        mma16816(d0[2], a0, &b1[0]);
        mma16816(d0[3], a0, &b1[2]);
        mma16816(d1[0], a1, &b1[0]);    // rows 16-31, cols 16-23
        mma16816(d1[1], a1, &b1[2]);    // rows 16-31, cols 24-31
    };

#pragma unroll 1
    for (int it = 0; it < NT; it += 2) {
        do_tile(it,     pfA, smt,          smtu);
        do_tile(it + 1, pfB, smt + TBYTES, smtu + TBYTES);
    }

    // column sums: reduce lane-replicas (lane bits 3,4)
#pragma unroll
    for (int off = 8; off <= 16; off <<= 1) {
        ssum.x += __shfl_xor_sync(0xffffffffu, ssum.x, off);
        ssum.y += __shfl_xor_sync(0xffffffffu, ssum.y, off);
        ssum.z += __shfl_xor_sync(0xffffffffu, ssum.z, off);
        ssum.w += __shfl_xor_sync(0xffffffffu, ssum.w, off);
    }
    if (lane < 8) swsum[w][lane] = ssum;
    __syncthreads();   // compute done: smt becomes `part`

    const int r0 = lane >> 2;
    const int jc = (lane & 3) * 2;

    // ---- h = 0: Gram rows 0..15 ----
#pragma unroll
    for (int nt = 0; nt < 4; nt++) {
        const int j0 = nt * 8 + jc;
        *(float2*)&part[w * PST + r0 * PRS + j0]       = make_float2(d0[nt][0], d0[nt][1]);
        *(float2*)&part[w * PST + (r0 + 8) * PRS + j0] = make_float2(d0[nt][2], d0[nt][3]);
    }
    __syncthreads();
    {
        const int e = tid;
        float v = 0.f;
#pragma unroll
        for (int w2 = 0; w2 < 16; w2++)
            v += part[w2 * PST + (e >> 5) * PRS + (e & 31)];
        g_Gp[chunk][t][e] = v;                        // unique writer
    }
    if (tid < 32) {
        float v = 0.f;
#pragma unroll
        for (int w2 = 0; w2 < 16; w2++)
            v += ((const float*)&swsum[w2][tid >> 2])[tid & 3];
        g_sp[chunk][t * CC + tid] = v;                // col index == tid
    }
    __syncthreads();

    // ---- h = 1: Gram rows 16..31 (cols 0..15 via symmetry transpose) ----
#pragma unroll
    for (int nt2 = 0; nt2 < 2; nt2++) {
        const int j0 = (nt2 + 2) * 8 + jc;
        *(float2*)&part[w * PST + r0 * PRS + j0]       = make_float2(d1[nt2][0], d1[nt2][1]);
        *(float2*)&part[w * PST + (r0 + 8) * PRS + j0] = make_float2(d1[nt2][2], d1[nt2][3]);
    }
#pragma unroll
    for (int nt = 2; nt < 4; nt++)
#pragma unroll
        for (int k = 0; k < 4; k++) {
            const int col_o = nt * 8 + jc + (k & 1);
            const int row_o = r0 + 8 * (k >> 1);
            part[w * PST + (col_o - 16) * PRS + row_o] = d0[nt][k];
        }
    __syncthreads();
    {
        const int e = tid;
        float v = 0.f;
#pragma unroll
        for (int w2 = 0; w2 < 16; w2++)
            v += part[w2 * PST + (e >> 5) * PRS + (e & 31)];
        g_Gp[chunk][t][512 + e] = v;                  // unique writer
    }

    // ---------- Phase B: per-t ticket; last chunk-CTA finalizes t ----------
    __threadfence();
    __syncthreads();
    if (tid == 0) s_tk = atomicAdd(&g_ctrs[t], 1);
    __syncthreads();
    if (s_tk != CH - 1) return;          // uniform exit for early CTAs
    __threadfence();                     // acquire: see the other chunk's partials
    if (tid == 0) g_ctrs[t] = 0;         // reset for next graph replay

    // finalize buffers alias smt (tile data dead)
    float* Ms  = (float*)smt;            // 800  (32 x 25 padded)
    float* Gs  = Ms + 800;               // 1024
    float* Asf = Gs + 1024;              // 1056 (32 x 33 padded)
    float* ss  = Asf + 1056;             // 32
    float* ks  = ss + 32;                // 32
    float* red = ks + 32;                // 16
    float* tl  = red + 16;               // 64
    float* hh  = tl + 64;                // 48   (3072 floats total)

    for (int idx = tid; idx < CC * HDIM; idx += THREADS)
        Ms[(idx / HDIM) * MSR + (idx % HDIM)] = Wt[t * CC * HDIM + idx];
    for (int e = tid; e < CC * CC; e += THREADS) {
        Gs[e] = g_Gp[0][t][e] + g_Gp[1][t][e];       // L2-hot
    }
    if (tid < CC) ss[tid] = g_sp[0][t * CC + tid] + g_sp[1][t * CC + tid];
    __syncthreads();

    // k vector (warp 0)
    if (tid < CC) {
        float kc = vb[t * CC + tid];
#pragma unroll
        for (int h = 0; h < HDIM; h++) kc += hb[t * HDIM + h] * Ms[tid * MSR + h];
        ks[tid] = kc;
    }

    // A = M M^T - I : each thread 2 elements (i, j0..j0+1)
    const int i  = tid >> 4;             // 0..31
    const int j0 = (tid & 15) * 2;       // 0,2,...,30
    {
        float acc0 = 0.f, acc1 = 0.f;
#pragma unroll
        for (int h = 0; h < HDIM; h++) {
            float mi = Ms[i * MSR + h];
            acc0 += mi * Ms[j0 * MSR + h];
            acc1 += mi * Ms[(j0 + 1) * MSR + h];
        }
        Asf[i * 33 + j0]     = acc0 - ((i == j0)     ? 1.f : 0.f);
        Asf[i * 33 + j0 + 1] = acc1 - ((i == j0 + 1) ? 1.f : 0.f);
    }
    __syncthreads();

    // quad partial: P_ij = row_i(A).row_j(A), contrib += G_ij * P_ij
    float pv = 0.f;
    {
        float acc0 = 0.f, acc1 = 0.f;
#pragma unroll
        for (int l = 0; l < CC; l++) {
            float ai = Asf[i * 33 + l];
            acc0 += ai * Asf[j0 * 33 + l];
            acc1 += ai * Asf[(j0 + 1) * 33 + l];
        }
        pv = Gs[i * CC + j0] * acc0 + Gs[i * CC + j0 + 1] * acc1;
    }
    // linear + constant (warp 0): k_c * (2 (A s)_c + B k_c)
    if (tid < CC) {
        float vs = 0.f;
#pragma unroll
        for (int l = 0; l < CC; l++) vs += Asf[tid * 33 + l] * ss[l];
        pv += ks[tid] * (2.f * vs + (float)BB * ks[tid]);
    }

    // block reduction (16 warps)
#pragma unroll
    for (int off = 16; off; off >>= 1)
        pv += __shfl_xor_sync(0xffffffffu, pv, off);
    if (lane == 0) red[w] = pv;
    __syncthreads();
    if (tid == 0) {
        float ssr = 0.f;
#pragma unroll
        for (int ww = 0; ww < 16; ww++) ssr += red[ww];
        float msr  = ssr * (1.f / (float)(BB * CC));
        float tail = 0.5f * logf(msr);
        g_tails[t] = tail;
        out[TT + t] = tail;                // tails occupy out[64..127]
    }

    // ---------- Phase C: global ticket; last finalizing CTA computes head ----------
    __threadfence();
    __syncthreads();
    if (tid == 0) s_tk = atomicAdd(&g_ctr, 1);
    __syncthreads();
    if (s_tk != TT - 1) return;
    __threadfence();                       // acquire: see all g_tails
    if (tid == 0) g_ctr = 0;               // reset for next graph replay

    if (tid < TT) tl[tid] = g_tails[tid];
    __syncthreads();
    if (tid < HHEAD) {
        float accv = hbh[tid];
#pragma unroll 8
        for (int u = 0; u < TT; u++) accv += tl[u] * Wh[u * HHEAD + tid];
        hh[tid] = accv;
    }
    __syncthreads();
    if (tid < TT) {
        float accv = vbh[tid];
#pragma unroll 8
        for (int jj = 0; jj < HHEAD; jj++) accv += hh[jj] * Wh[tid * HHEAD + jj];
        out[tid] = accv;                   // head_out occupies out[0..63]
    }
}

extern "C" void kernel_launch(void* const* d_in, const int* in_sizes, int n_in,
                              void* d_out, int out_size) {
    const float* x        = (const float*)d_in[0];
    const int*   clusters = (const int*)  d_in[1];
    const float* Wt       = (const float*)d_in[2];
    const float* hb       = (const float*)d_in[3];
    const float* vb       = (const float*)d_in[4];
    const float* Wh       = (const float*)d_in[5];
    const float* hbh      = (const float*)d_in[6];
    const float* vbh      = (const float*)d_in[7];
    float* out = (float*)d_out;

    gram_kernel<<<dim3(TT, CH), THREADS>>>(x, clusters, Wt, hb, vb, Wh, hbh, vbh, out);
}